// round 6
// baseline (speedup 1.0000x reference)
#include <cuda_runtime.h>

#define HH 512
#define WW 512
#define NB 8
#define CC 8
#define RR 32          // output rows per warp-tile
#define OC 28          // output cols per warp-tile (32 lanes - 4 halo)
#define XT 19          // ceil(512/28)
#define BANDS 16       // 512 / RR
#define WPB 4          // warps per block
#define NTILES (XT * BANDS * NB)    // 2432
#define NBLOCKS (NTILES / WPB)      // 608

__device__ double g_acc[3];
__device__ unsigned g_ctr = 0;

__device__ __forceinline__ int reflect_i(int t) {
    if (t < 0) t = -t;
    if (t >= HH) t = 2 * HH - 2 - t;
    return t;
}

__global__ __launch_bounds__(128)
void fused_loss_kernel(const float* __restrict__ pan,
                       const float* __restrict__ ms,
                       const float* __restrict__ out,
                       float* __restrict__ o) {
    const int lane = threadIdx.x & 31;
    const int wid  = threadIdx.x >> 5;
    const int g    = blockIdx.x * WPB + wid;     // warp-tile id, < NTILES
    const int xt   = g % XT;
    const int band = (g / XT) % BANDS;
    const int n    = g / (XT * BANDS);

    const int x_l  = xt * OC + lane - 2;              // this lane's column
    const bool mx  = (x_l >= 0) && (x_l < WW);        // in-image column
    const int x_r  = (x_l < 0) ? -x_l : ((x_l >= WW) ? (2 * WW - 2 - x_l) : x_l);
    const bool outlane = (lane >= 2) && (lane < 30) && mx;

    const int gy0 = band * RR;
    const size_t HW = (size_t)HH * WW;

    const float gw0 = 0.15246914f, gw1 = 0.22184130f, gw2 = 0.25137913f;

    float mean_acc[RR + 2];
    #pragma unroll
    for (int i = 0; i < RR + 2; ++i) mean_acc[i] = 0.f;

    float acc1 = 0.f;

    const float* out_n = out + (size_t)n * CC * HW;
    const float* ms_n  = ms  + (size_t)n * CC * HW;

    #pragma unroll 1
    for (int c = 0; c < CC; ++c) {
        const float* oc_ = out_n + (size_t)c * HW + x_r;
        const float* mc_ = ms_n  + (size_t)c * HW + x_l;
        float w0 = 0.f, w1 = 0.f, w2 = 0.f, w3 = 0.f, w4 = 0.f;
        #pragma unroll
        for (int j = 0; j < RR + 4; ++j) {
            const int gy  = gy0 - 2 + j;
            const int gyr = reflect_i(gy);
            const float v = oc_[(size_t)gyr * WW];          // blur input (reflect pad)
            if (j >= 1 && j <= RR + 2) {
                if (mx && gy >= 0 && gy < HH) mean_acc[j - 1] += v;  // zero pad
            }
            w0 = w1; w1 = w2; w2 = w3; w3 = w4; w4 = v;
            if (j >= 4) {
                const float vb = gw0 * (w0 + w4) + gw1 * (w1 + w3) + gw2 * w2;
                const float u2 = __shfl_up_sync(0xFFFFFFFFu, vb, 2);
                const float u1 = __shfl_up_sync(0xFFFFFFFFu, vb, 1);
                const float d1 = __shfl_down_sync(0xFFFFFFFFu, vb, 1);
                const float d2 = __shfl_down_sync(0xFFFFFFFFu, vb, 2);
                const float hb = gw0 * (u2 + d2) + gw1 * (u1 + d1) + gw2 * vb;
                const int r = j - 4;
                if (outlane) {
                    const float msv = mc_[(size_t)(gy0 + r) * WW];
                    acc1 += fabsf(hb - msv);
                }
            }
        }
    }

    // ---- sobel: mean (zero pad, /8 folded as 0.125) vs pan (zero pad) ----
    const float* pan_n = pan + (size_t)n * HW;
    float acc2 = 0.f, acc3 = 0.f;
    float p0 = 0.f, p1 = 0.f, p2 = 0.f;
    #pragma unroll
    for (int j = 0; j < RR + 2; ++j) {
        const int gy = gy0 - 1 + j;
        float pv = 0.f;
        if (mx && gy >= 0 && gy < HH) pv = pan_n[(size_t)gy * WW + x_l];
        p0 = p1; p1 = p2; p2 = pv;
        if (j >= 2) {
            const int r = j - 2;
            const float sxm = mean_acc[r] + 2.f * mean_acc[r + 1] + mean_acc[r + 2];
            const float sym = mean_acc[r + 2] - mean_acc[r];
            const float ogx = (__shfl_down_sync(0xFFFFFFFFu, sxm, 1)
                             - __shfl_up_sync(0xFFFFFFFFu, sxm, 1)) * 0.125f;
            const float ogy = (__shfl_up_sync(0xFFFFFFFFu, sym, 1) + 2.f * sym
                             + __shfl_down_sync(0xFFFFFFFFu, sym, 1)) * 0.125f;
            const float sxp = p0 + 2.f * p1 + p2;
            const float syp = p2 - p0;
            const float pgx = __shfl_down_sync(0xFFFFFFFFu, sxp, 1)
                            - __shfl_up_sync(0xFFFFFFFFu, sxp, 1);
            const float pgy = __shfl_up_sync(0xFFFFFFFFu, syp, 1) + 2.f * syp
                            + __shfl_down_sync(0xFFFFFFFFu, syp, 1);
            if (outlane) {
                acc2 += fabsf(ogx - pgx);
                acc3 += fabsf(ogy - pgy);
            }
        }
    }

    // ---- warp reduce, then block reduce, then global atomics ----
    #pragma unroll
    for (int o2 = 16; o2 > 0; o2 >>= 1) {
        acc1 += __shfl_down_sync(0xFFFFFFFFu, acc1, o2);
        acc2 += __shfl_down_sync(0xFFFFFFFFu, acc2, o2);
        acc3 += __shfl_down_sync(0xFFFFFFFFu, acc3, o2);
    }
    __shared__ float sred[3][WPB];
    if (lane == 0) { sred[0][wid] = acc1; sred[1][wid] = acc2; sred[2][wid] = acc3; }
    __syncthreads();
    if (threadIdx.x == 0) {
        double a = 0.0, b = 0.0, c = 0.0;
        #pragma unroll
        for (int w = 0; w < WPB; ++w) {
            a += (double)sred[0][w];
            b += (double)sred[1][w];
            c += (double)sred[2][w];
        }
        atomicAdd(&g_acc[0], a);
        atomicAdd(&g_acc[1], b);
        atomicAdd(&g_acc[2], c);
        __threadfence();
        unsigned t = atomicAdd(&g_ctr, 1u);
        if (t == NBLOCKS - 1) {
            __threadfence();
            double loss = g_acc[0] * (1.0 / 16777216.0)
                        + (g_acc[1] + g_acc[2]) * (1.0 / 2097152.0);
            o[0] = (float)loss;
            g_acc[0] = 0.0; g_acc[1] = 0.0; g_acc[2] = 0.0;
            g_ctr = 0;                      // reset for next graph replay
        }
    }
}

extern "C" void kernel_launch(void* const* d_in, const int* in_sizes, int n_in,
                              void* d_out, int out_size) {
    const float* pan = (const float*)d_in[0];
    const float* ms  = (const float*)d_in[1];
    const float* out = (const float*)d_in[2];
    if (n_in == 3 && in_sizes[0] != 2097152) {
        for (int i = 0; i < 3; ++i) {
            if (in_sizes[i] == 2097152) {
                pan = (const float*)d_in[i];
                int others[2], k = 0;
                for (int j = 0; j < 3; ++j) if (j != i) others[k++] = j;
                ms  = (const float*)d_in[others[0]];
                out = (const float*)d_in[others[1]];
                break;
            }
        }
    }

    fused_loss_kernel<<<NBLOCKS, 128>>>(pan, ms, out, (float*)d_out);
}

// round 7
// speedup vs baseline: 2.2540x; 2.2540x over previous
#include <cuda_runtime.h>
#include <cstdint>

#define HH 512
#define WW 512
#define NB 8
#define CC 8
#define OC 28          // output cols per block (lanes 2..29)
#define ICOLS 36       // staged input cols (aligned at xa = 28*xt - 4)
#define ORS 128        // output rows per block
#define IRS 132        // staged input rows (2-halo)
#define XT 19          // ceil(512/28)
#define BANDS 4        // 512/128
#define NBLOCKS (XT * BANDS * NB)   // 608
#define NVEC (IRS * 9)              // 16B vectors per channel tile = 1188

// smem (floats)
#define SBUF_STRIDE 4752            // 132*36
#define SM_B0   0
#define SM_B1   4752
#define SM_MEAN 9504                // 130 rows x 32 cols = 4160
#define SM_RED  13664               // 96
#define SM_FLOATS 13792
#define SMEM_BYTES (SM_FLOATS * 4)

__device__ double g_acc[3];
__device__ unsigned g_ctr = 0;

__device__ __forceinline__ int reflect_i(int t) {
    if (t < 0) t = -t;
    if (t >= HH) t = 2 * HH - 2 - t;
    return t;
}
__device__ __forceinline__ int reflect_x(int t) {
    if (t < 0) t = -t;
    if (t >= WW) t = 2 * WW - 2 - t;
    return t;
}
__device__ __forceinline__ void cp16(uint32_t s, const float* g) {
    asm volatile("cp.async.cg.shared.global [%0], [%1], 16;" :: "r"(s), "l"(g));
}
__device__ __forceinline__ void cp4(uint32_t s, const float* g) {
    asm volatile("cp.async.ca.shared.global [%0], [%1], 4;" :: "r"(s), "l"(g));
}
__device__ __forceinline__ void cp_commit() {
    asm volatile("cp.async.commit_group;" ::: "memory");
}

__global__ __launch_bounds__(1024)
void fused_loss_kernel(const float* __restrict__ pan,
                       const float* __restrict__ ms,
                       const float* __restrict__ out,
                       float* __restrict__ o) {
    extern __shared__ float sm[];
    float* s_mean = sm + SM_MEAN;
    float* s_red  = sm + SM_RED;

    const int tid  = threadIdx.x;
    const int lane = tid & 31;
    const int wid  = tid >> 5;
    const int r0   = wid * 4;                 // this warp's first output row (tile-local)

    const int xt   = blockIdx.x % XT;
    const int band = (blockIdx.x / XT) % BANDS;
    const int n    = blockIdx.x / (XT * BANDS);

    const int gy0 = band * ORS;
    const int xa  = xt * OC - 4;              // 16B-aligned staging base col
    const int col_l = xa + 2 + lane;          // this lane's image column
    const bool colok = (col_l >= 0) && (col_l < WW);
    const bool outl  = (lane >= 2) && (lane <= 29) && colok;

    const size_t HW = (size_t)HH * WW;
    const float gw0 = 0.15246914f, gw1 = 0.22184130f, gw2 = 0.25137913f;

    const float* out_n = out + (size_t)n * CC * HW;
    const float* ms_n  = ms  + (size_t)n * CC * HW;
    const float* pan_n = pan + (size_t)n * HW;

    // ---- hoisted staging coordinates (2 vectors/thread max) ----
    const int v0 = tid,  v1 = tid + 1024;
    const bool hv1 = (v1 < NVEC);             // tid < 164
    const int row0 = v0 / 9, vx0 = v0 % 9;
    const int row1 = hv1 ? v1 / 9 : 0, vx1 = hv1 ? v1 % 9 : 0;
    const int grow0 = reflect_i(gy0 - 2 + row0);
    const int grow1 = reflect_i(gy0 - 2 + row1);
    const int gc0_0 = xa + 4 * vx0;
    const int gc0_1 = xa + 4 * vx1;
    const bool in0 = (gc0_0 >= 0) && (gc0_0 <= WW - 4);
    const bool in1 = (gc0_1 >= 0) && (gc0_1 <= WW - 4);
    const uint32_t smbase = (uint32_t)__cvta_generic_to_shared(sm);
    const uint32_t d0 = smbase + (uint32_t)(row0 * ICOLS + vx0 * 4) * 4;
    const uint32_t d1 = smbase + (uint32_t)(row1 * ICOLS + vx1 * 4) * 4;

    #define STAGE(ch, bufoff) do {                                              \
        const float* src = out_n + (size_t)(ch) * HW;                           \
        const float* g0p = src + (size_t)grow0 * WW + gc0_0;                    \
        if (in0) cp16(d0 + (bufoff), g0p);                                      \
        else {                                                                  \
            _Pragma("unroll")                                                   \
            for (int k = 0; k < 4; ++k)                                         \
                cp4(d0 + (bufoff) + k * 4,                                      \
                    src + (size_t)grow0 * WW + reflect_x(gc0_0 + k));           \
        }                                                                       \
        if (hv1) {                                                              \
            const float* g1p = src + (size_t)grow1 * WW + gc0_1;                \
            if (in1) cp16(d1 + (bufoff), g1p);                                  \
            else {                                                              \
                _Pragma("unroll")                                               \
                for (int k = 0; k < 4; ++k)                                     \
                    cp4(d1 + (bufoff) + k * 4,                                  \
                        src + (size_t)grow1 * WW + reflect_x(gc0_1 + k));       \
            }                                                                   \
        }                                                                       \
        cp_commit();                                                            \
    } while (0)

    // ---- prologue: stage ch0, ch1 ----
    STAGE(0, 0);
    STAGE(1, SBUF_STRIDE * 4);

    float m0 = 0.f, m1 = 0.f, m2 = 0.f, m3 = 0.f;   // channel-sum (4 out rows)
    float m_top = 0.f, m_bot = 0.f;                  // halo rows (warp 0 / 31)
    const bool top_in = (band > 0);
    const bool bot_in = (band < BANDS - 1);
    float acc1 = 0.f;

    #pragma unroll 1
    for (int c = 0; c < CC; ++c) {
        asm volatile("cp.async.wait_group 1;" ::: "memory");
        __syncthreads();
        const float* sb = sm + (c & 1) * SBUF_STRIDE;
        const float* mc = ms_n + (size_t)c * HW;

        float w0, w1, w2, w3, w4;
        w0 = w1 = w2 = w3 = w4 = 0.f;
        #pragma unroll
        for (int j = 0; j < 8; ++j) {
            const float v = sb[(r0 + j) * ICOLS + 2 + lane];
            if (colok) {
                if (j == 2) m0 += v;
                if (j == 3) m1 += v;
                if (j == 4) m2 += v;
                if (j == 5) m3 += v;
                if (j == 1 && wid == 0  && top_in) m_top += v;
                if (j == 6 && wid == 31 && bot_in) m_bot += v;
            }
            w0 = w1; w1 = w2; w2 = w3; w3 = w4; w4 = v;
            if (j >= 4) {
                const float vb = gw0 * (w0 + w4) + gw1 * (w1 + w3) + gw2 * w2;
                const float u2 = __shfl_up_sync(0xFFFFFFFFu, vb, 2);
                const float u1 = __shfl_up_sync(0xFFFFFFFFu, vb, 1);
                const float dn1 = __shfl_down_sync(0xFFFFFFFFu, vb, 1);
                const float dn2 = __shfl_down_sync(0xFFFFFFFFu, vb, 2);
                const float hb = gw0 * (u2 + dn2) + gw1 * (u1 + dn1) + gw2 * vb;
                if (outl) {
                    const int orow = gy0 + r0 + j - 4;
                    acc1 += fabsf(hb - mc[(size_t)orow * WW + col_l]);
                }
            }
        }
        __syncthreads();                 // everyone done reading buf before restage
        if (c + 2 < CC) STAGE(c + 2, (c & 1) * SBUF_STRIDE * 4);
    }

    // ---- write mean tile (rows: tile-local -1..128 -> index 0..129) ----
    s_mean[(r0 + 1) * 32 + lane] = m0;
    s_mean[(r0 + 2) * 32 + lane] = m1;
    s_mean[(r0 + 3) * 32 + lane] = m2;
    s_mean[(r0 + 4) * 32 + lane] = m3;
    if (wid == 0)  s_mean[lane] = m_top;
    if (wid == 31) s_mean[129 * 32 + lane] = m_bot;
    __syncthreads();

    // ---- sobel: mean (x0.125) vs pan, rolling + shfl ----
    float acc2 = 0.f, acc3 = 0.f;
    {
        float q0 = 0.f, q1 = 0.f, q2 = 0.f;
        float p0 = 0.f, p1 = 0.f, p2 = 0.f;
        #pragma unroll
        for (int j = 0; j < 6; ++j) {
            const float qv = s_mean[(r0 + j) * 32 + lane];
            const int grow = gy0 + r0 - 1 + j;
            float pv = 0.f;
            if (colok && grow >= 0 && grow < HH)
                pv = pan_n[(size_t)grow * WW + col_l];
            q0 = q1; q1 = q2; q2 = qv;
            p0 = p1; p1 = p2; p2 = pv;
            if (j >= 2) {
                const float sxm = q0 + 2.f * q1 + q2;
                const float sym = q2 - q0;
                const float ogx = (__shfl_down_sync(0xFFFFFFFFu, sxm, 1)
                                 - __shfl_up_sync(0xFFFFFFFFu, sxm, 1)) * 0.125f;
                const float ogy = (__shfl_up_sync(0xFFFFFFFFu, sym, 1) + 2.f * sym
                                 + __shfl_down_sync(0xFFFFFFFFu, sym, 1)) * 0.125f;
                const float sxp = p0 + 2.f * p1 + p2;
                const float syp = p2 - p0;
                const float pgx = __shfl_down_sync(0xFFFFFFFFu, sxp, 1)
                                - __shfl_up_sync(0xFFFFFFFFu, sxp, 1);
                const float pgy = __shfl_up_sync(0xFFFFFFFFu, syp, 1) + 2.f * syp
                                + __shfl_down_sync(0xFFFFFFFFu, syp, 1);
                if (outl) {
                    acc2 += fabsf(ogx - pgx);
                    acc3 += fabsf(ogy - pgy);
                }
            }
        }
    }

    // ---- reduction ----
    #pragma unroll
    for (int o2 = 16; o2 > 0; o2 >>= 1) {
        acc1 += __shfl_down_sync(0xFFFFFFFFu, acc1, o2);
        acc2 += __shfl_down_sync(0xFFFFFFFFu, acc2, o2);
        acc3 += __shfl_down_sync(0xFFFFFFFFu, acc3, o2);
    }
    if (lane == 0) { s_red[wid] = acc1; s_red[32 + wid] = acc2; s_red[64 + wid] = acc3; }
    __syncthreads();
    if (wid == 0) {
        float a = s_red[lane], b = s_red[32 + lane], cc2 = s_red[64 + lane];
        #pragma unroll
        for (int o2 = 16; o2 > 0; o2 >>= 1) {
            a   += __shfl_down_sync(0xFFFFFFFFu, a,   o2);
            b   += __shfl_down_sync(0xFFFFFFFFu, b,   o2);
            cc2 += __shfl_down_sync(0xFFFFFFFFu, cc2, o2);
        }
        if (lane == 0) {
            atomicAdd(&g_acc[0], (double)a);
            atomicAdd(&g_acc[1], (double)b);
            atomicAdd(&g_acc[2], (double)cc2);
            __threadfence();
            unsigned t = atomicAdd(&g_ctr, 1u);
            if (t == NBLOCKS - 1) {
                __threadfence();
                double loss = g_acc[0] * (1.0 / 16777216.0)
                            + (g_acc[1] + g_acc[2]) * (1.0 / 2097152.0);
                o[0] = (float)loss;
                g_acc[0] = 0.0; g_acc[1] = 0.0; g_acc[2] = 0.0;
                g_ctr = 0;                      // reset for next graph replay
            }
        }
    }
}

extern "C" void kernel_launch(void* const* d_in, const int* in_sizes, int n_in,
                              void* d_out, int out_size) {
    const float* pan = (const float*)d_in[0];
    const float* ms  = (const float*)d_in[1];
    const float* out = (const float*)d_in[2];
    if (n_in == 3 && in_sizes[0] != 2097152) {
        for (int i = 0; i < 3; ++i) {
            if (in_sizes[i] == 2097152) {
                pan = (const float*)d_in[i];
                int others[2], k = 0;
                for (int j = 0; j < 3; ++j) if (j != i) others[k++] = j;
                ms  = (const float*)d_in[others[0]];
                out = (const float*)d_in[others[1]];
                break;
            }
        }
    }

    static bool attr_done = false;
    if (!attr_done) {
        cudaFuncSetAttribute(fused_loss_kernel,
                             cudaFuncAttributeMaxDynamicSharedMemorySize, SMEM_BYTES);
        attr_done = true;
    }

    fused_loss_kernel<<<NBLOCKS, 1024, SMEM_BYTES>>>(pan, ms, out, (float*)d_out);
}

// round 9
// speedup vs baseline: 3.1586x; 1.4013x over previous
#include <cuda_runtime.h>
#include <cstdint>

#define HH 512
#define WW 512
#define NB 8
#define CC 8
#define OC 28          // output cols per block (lanes 2..29)
#define ICOLS 36       // staged input cols
#define ORS 32         // output rows per block
#define IRS 36         // staged input rows (2-halo)
#define XT 19          // ceil(512/28)
#define BANDS 16       // 512/32
#define NBLOCKS (XT * BANDS * NB)   // 2432
#define NVEC (IRS * 9)              // 324 16B vectors per channel tile

// smem (floats)
#define SBUF_STRIDE 1296            // 36*36
#define SM_MEAN 2592                // 34 rows x 32 cols = 1088
#define SM_RED  3680                // 24
#define SM_FLOATS 3712
#define SMEM_BYTES (SM_FLOATS * 4)

__device__ double g_acc[3];
__device__ unsigned g_ctr = 0;

__device__ __forceinline__ int reflect_i(int t) {
    if (t < 0) t = -t;
    if (t >= HH) t = 2 * HH - 2 - t;
    return t;
}
__device__ __forceinline__ int reflect_x(int t) {
    if (t < 0) t = -t;
    if (t >= WW) t = 2 * WW - 2 - t;
    return t;
}
__device__ __forceinline__ void cp16(uint32_t s, const float* g) {
    asm volatile("cp.async.cg.shared.global [%0], [%1], 16;" :: "r"(s), "l"(g));
}
__device__ __forceinline__ void cp4(uint32_t s, const float* g) {
    asm volatile("cp.async.ca.shared.global [%0], [%1], 4;" :: "r"(s), "l"(g));
}
__device__ __forceinline__ void cp_commit() {
    asm volatile("cp.async.commit_group;" ::: "memory");
}

__global__ __launch_bounds__(256)
void fused_loss_kernel(const float* __restrict__ pan,
                       const float* __restrict__ ms,
                       const float* __restrict__ out,
                       float* __restrict__ o) {
    extern __shared__ float sm[];
    float* s_mean = sm + SM_MEAN;
    float* s_red  = sm + SM_RED;

    const int tid  = threadIdx.x;
    const int lane = tid & 31;
    const int wid  = tid >> 5;                // 0..7
    const int r0   = wid * 4;                 // warp's first output row (tile-local)

    const int xt   = blockIdx.x % XT;
    const int band = (blockIdx.x / XT) % BANDS;
    const int n    = blockIdx.x / (XT * BANDS);

    const int gy0 = band * ORS;
    const int xa  = xt * OC - 4;              // 16B-aligned staging base col
    const int col_l = xa + 2 + lane;
    const bool colok = (col_l >= 0) && (col_l < WW);
    const bool outl  = (lane >= 2) && (lane <= 29) && colok;

    const size_t HW = (size_t)HH * WW;
    const float gw0 = 0.15246914f, gw1 = 0.22184130f, gw2 = 0.25137913f;

    const float* out_n = out + (size_t)n * CC * HW;
    const float* pan_n = pan + (size_t)n * HW;
    // ms pointer for this thread's 4 output rows (row gy0+r0 .. +3, col col_l)
    const float* ms_t = ms + (size_t)n * CC * HW
                      + (size_t)(gy0 + r0) * WW + (outl ? col_l : 0);

    // ---- staging coordinates (<=2 vectors/thread) ----
    const int v0 = tid, v1 = tid + 256;
    const bool hv1 = (v1 < NVEC);             // tid < 68
    const int row0 = v0 / 9, vx0 = v0 % 9;
    const int row1 = hv1 ? v1 / 9 : 0, vx1 = hv1 ? v1 % 9 : 0;
    const int grow0 = reflect_i(gy0 - 2 + row0);
    const int grow1 = reflect_i(gy0 - 2 + row1);
    const int gc0_0 = xa + 4 * vx0;
    const int gc0_1 = xa + 4 * vx1;
    const bool in0 = (gc0_0 >= 0) && (gc0_0 <= WW - 4);
    const bool in1 = (gc0_1 >= 0) && (gc0_1 <= WW - 4);
    const bool hasv0 = (v0 < NVEC);           // always true (256 < 324)
    const uint32_t smbase = (uint32_t)__cvta_generic_to_shared(sm);
    const uint32_t d0 = smbase + (uint32_t)(row0 * ICOLS + vx0 * 4) * 4;
    const uint32_t d1 = smbase + (uint32_t)(row1 * ICOLS + vx1 * 4) * 4;

    #define STAGE(ch, bufoff) do {                                              \
        const float* src = out_n + (size_t)(ch) * HW;                           \
        if (hasv0) {                                                            \
            if (in0) cp16(d0 + (bufoff), src + (size_t)grow0 * WW + gc0_0);     \
            else {                                                              \
                _Pragma("unroll")                                               \
                for (int k = 0; k < 4; ++k)                                     \
                    cp4(d0 + (bufoff) + k * 4,                                  \
                        src + (size_t)grow0 * WW + reflect_x(gc0_0 + k));       \
            }                                                                   \
        }                                                                       \
        if (hv1) {                                                              \
            if (in1) cp16(d1 + (bufoff), src + (size_t)grow1 * WW + gc0_1);     \
            else {                                                              \
                _Pragma("unroll")                                               \
                for (int k = 0; k < 4; ++k)                                     \
                    cp4(d1 + (bufoff) + k * 4,                                  \
                        src + (size_t)grow1 * WW + reflect_x(gc0_1 + k));       \
            }                                                                   \
        }                                                                       \
        cp_commit();                                                            \
    } while (0)

    // ---- prologue: stage ch0, ch1; prefetch ms ch0 ----
    STAGE(0, 0);
    STAGE(1, SBUF_STRIDE * 4);

    float msr0 = 0.f, msr1 = 0.f, msr2 = 0.f, msr3 = 0.f;
    if (outl) {
        msr0 = __ldg(ms_t);
        msr1 = __ldg(ms_t + WW);
        msr2 = __ldg(ms_t + 2 * WW);
        msr3 = __ldg(ms_t + 3 * WW);
    }

    float m0 = 0.f, m1 = 0.f, m2 = 0.f, m3 = 0.f;
    float m_top = 0.f, m_bot = 0.f;
    const bool top_in = (gy0 > 0);
    const bool bot_in = (gy0 + ORS < HH);
    float acc1 = 0.f;

    #pragma unroll 1
    for (int c = 0; c < CC; ++c) {
        asm volatile("cp.async.wait_group 1;" ::: "memory");
        __syncthreads();
        const float* sb = sm + (c & 1) * SBUF_STRIDE;

        // prefetch next channel's ms values (overlaps compute below)
        float nx0 = 0.f, nx1 = 0.f, nx2 = 0.f, nx3 = 0.f;
        if (c + 1 < CC && outl) {
            const float* mn = ms_t + (size_t)(c + 1) * HW;
            nx0 = __ldg(mn);
            nx1 = __ldg(mn + WW);
            nx2 = __ldg(mn + 2 * WW);
            nx3 = __ldg(mn + 3 * WW);
        }

        float w0, w1, w2, w3, w4;
        w0 = w1 = w2 = w3 = w4 = 0.f;
        #pragma unroll
        for (int j = 0; j < 8; ++j) {
            const float v = sb[(r0 + j) * ICOLS + 2 + lane];
            if (colok) {
                if (j == 2) m0 += v;
                if (j == 3) m1 += v;
                if (j == 4) m2 += v;
                if (j == 5) m3 += v;
                if (j == 1 && wid == 0 && top_in) m_top += v;
                if (j == 6 && wid == 7 && bot_in) m_bot += v;
            }
            w0 = w1; w1 = w2; w2 = w3; w3 = w4; w4 = v;
            if (j >= 4) {
                const float vb = gw0 * (w0 + w4) + gw1 * (w1 + w3) + gw2 * w2;
                const float u2 = __shfl_up_sync(0xFFFFFFFFu, vb, 2);
                const float u1 = __shfl_up_sync(0xFFFFFFFFu, vb, 1);
                const float dn1 = __shfl_down_sync(0xFFFFFFFFu, vb, 1);
                const float dn2 = __shfl_down_sync(0xFFFFFFFFu, vb, 2);
                const float hb = gw0 * (u2 + dn2) + gw1 * (u1 + dn1) + gw2 * vb;
                const float msv = (j == 4) ? msr0 : (j == 5) ? msr1
                                : (j == 6) ? msr2 : msr3;
                if (outl) acc1 += fabsf(hb - msv);
            }
        }
        msr0 = nx0; msr1 = nx1; msr2 = nx2; msr3 = nx3;
        __syncthreads();
        if (c + 2 < CC) STAGE(c + 2, (c & 1) * SBUF_STRIDE * 4);
    }

    // ---- write mean tile (34 rows: global gy0-1 .. gy0+32) ----
    s_mean[(r0 + 1) * 32 + lane] = m0;
    s_mean[(r0 + 2) * 32 + lane] = m1;
    s_mean[(r0 + 3) * 32 + lane] = m2;
    s_mean[(r0 + 4) * 32 + lane] = m3;
    if (wid == 0) s_mean[lane] = m_top;
    if (wid == 7) s_mean[33 * 32 + lane] = m_bot;
    __syncthreads();

    // ---- sobel: mean (x0.125) vs pan ----
    float acc2 = 0.f, acc3 = 0.f;
    {
        float q0 = 0.f, q1 = 0.f, q2 = 0.f;
        float p0 = 0.f, p1 = 0.f, p2 = 0.f;
        #pragma unroll
        for (int j = 0; j < 6; ++j) {
            const float qv = s_mean[(r0 + j) * 32 + lane];
            const int grow = gy0 + r0 - 1 + j;
            float pv = 0.f;
            if (colok && grow >= 0 && grow < HH)
                pv = pan_n[(size_t)grow * WW + col_l];
            q0 = q1; q1 = q2; q2 = qv;
            p0 = p1; p1 = p2; p2 = pv;
            if (j >= 2) {
                const float sxm = q0 + 2.f * q1 + q2;
                const float sym = q2 - q0;
                const float ogx = (__shfl_down_sync(0xFFFFFFFFu, sxm, 1)
                                 - __shfl_up_sync(0xFFFFFFFFu, sxm, 1)) * 0.125f;
                const float ogy = (__shfl_up_sync(0xFFFFFFFFu, sym, 1) + 2.f * sym
                                 + __shfl_down_sync(0xFFFFFFFFu, sym, 1)) * 0.125f;
                const float sxp = p0 + 2.f * p1 + p2;
                const float syp = p2 - p0;
                const float pgx = __shfl_down_sync(0xFFFFFFFFu, sxp, 1)
                                - __shfl_up_sync(0xFFFFFFFFu, sxp, 1);
                const float pgy = __shfl_up_sync(0xFFFFFFFFu, syp, 1) + 2.f * syp
                                + __shfl_down_sync(0xFFFFFFFFu, syp, 1);
                if (outl) {
                    acc2 += fabsf(ogx - pgx);
                    acc3 += fabsf(ogy - pgy);
                }
            }
        }
    }

    // ---- reduction ----
    #pragma unroll
    for (int o2 = 16; o2 > 0; o2 >>= 1) {
        acc1 += __shfl_down_sync(0xFFFFFFFFu, acc1, o2);
        acc2 += __shfl_down_sync(0xFFFFFFFFu, acc2, o2);
        acc3 += __shfl_down_sync(0xFFFFFFFFu, acc3, o2);
    }
    if (lane == 0) { s_red[wid] = acc1; s_red[8 + wid] = acc2; s_red[16 + wid] = acc3; }
    __syncthreads();
    if (tid == 0) {
        float a = 0.f, b = 0.f, cc2 = 0.f;
        #pragma unroll
        for (int w = 0; w < 8; ++w) {
            a += s_red[w]; b += s_red[8 + w]; cc2 += s_red[16 + w];
        }
        atomicAdd(&g_acc[0], (double)a);
        atomicAdd(&g_acc[1], (double)b);
        atomicAdd(&g_acc[2], (double)cc2);
        __threadfence();
        unsigned t = atomicAdd(&g_ctr, 1u);
        if (t == NBLOCKS - 1) {
            __threadfence();
            double loss = g_acc[0] * (1.0 / 16777216.0)
                        + (g_acc[1] + g_acc[2]) * (1.0 / 2097152.0);
            o[0] = (float)loss;
            g_acc[0] = 0.0; g_acc[1] = 0.0; g_acc[2] = 0.0;
            g_ctr = 0;                      // reset for next graph replay
        }
    }
}

extern "C" void kernel_launch(void* const* d_in, const int* in_sizes, int n_in,
                              void* d_out, int out_size) {
    const float* pan = (const float*)d_in[0];
    const float* ms  = (const float*)d_in[1];
    const float* out = (const float*)d_in[2];
    if (n_in == 3 && in_sizes[0] != 2097152) {
        for (int i = 0; i < 3; ++i) {
            if (in_sizes[i] == 2097152) {
                pan = (const float*)d_in[i];
                int others[2], k = 0;
                for (int j = 0; j < 3; ++j) if (j != i) others[k++] = j;
                ms  = (const float*)d_in[others[0]];
                out = (const float*)d_in[others[1]];
                break;
            }
        }
    }

    fused_loss_kernel<<<NBLOCKS, 256, SMEM_BYTES>>>(pan, ms, out, (float*)d_out);
}